// round 2
// baseline (speedup 1.0000x reference)
#include <cuda_runtime.h>

#define GD 10000          // vocab rows
#define GN 10001          // vocab rows + default slot
#define GH 1024           // hidden
#define GM 4096           // B * L
#define SEL_EPS 1e-10f
#define SEL_CAP 2048

// ---------------------------------------------------------------------------
// Kernel 1: logits[m, n] = desc[m, :] . full_vocab[n, :]
// full_vocab[n] = vocab[n] for n < GD, default_embedding for n == GD.
// Classic 128x128x16 fp32 SIMT GEMM, 256 threads, 8x8 per-thread microtile.
// ---------------------------------------------------------------------------
__global__ __launch_bounds__(256) void gemm1_logits(
    const float* __restrict__ desc,    // (GM, GH)
    const float* __restrict__ vocab,   // (GD, GH)
    const float* __restrict__ defemb,  // (GH)
    float* __restrict__ logits)        // (GM, GN)
{
    __shared__ float As[16][132];
    __shared__ float Bs[16][132];

    const int bm = blockIdx.y;
    const int bn = blockIdx.x;
    const int tid = threadIdx.x;
    const int tx = tid & 15;
    const int ty = tid >> 4;
    const int m0 = bm * 128;
    const int n0 = bn * 128;

    float acc[8][8];
    #pragma unroll
    for (int i = 0; i < 8; i++)
        #pragma unroll
        for (int j = 0; j < 8; j++) acc[i][j] = 0.0f;

    for (int kt = 0; kt < GH; kt += 16) {
        // Load A tile (128 rows x 16 cols), transposed into As[k][m]
        #pragma unroll
        for (int l = 0; l < 2; l++) {
            int idx = tid + l * 256;        // 0..511 float4 slots
            int row = idx >> 2;             // 0..127
            int c4  = idx & 3;
            const float4 a = *reinterpret_cast<const float4*>(
                &desc[(size_t)(m0 + row) * GH + kt + c4 * 4]);
            As[c4 * 4 + 0][row] = a.x;
            As[c4 * 4 + 1][row] = a.y;
            As[c4 * 4 + 2][row] = a.z;
            As[c4 * 4 + 3][row] = a.w;
        }
        // Load B tile (128 n-rows x 16 k-cols), transposed into Bs[k][n]
        #pragma unroll
        for (int l = 0; l < 2; l++) {
            int idx = tid + l * 256;
            int row = idx >> 2;
            int c4  = idx & 3;
            int n   = n0 + row;
            float4 b;
            if (n < GD) {
                b = *reinterpret_cast<const float4*>(
                    &vocab[(size_t)n * GH + kt + c4 * 4]);
            } else if (n == GD) {
                b = *reinterpret_cast<const float4*>(&defemb[kt + c4 * 4]);
            } else {
                b = make_float4(0.f, 0.f, 0.f, 0.f);
            }
            Bs[c4 * 4 + 0][row] = b.x;
            Bs[c4 * 4 + 1][row] = b.y;
            Bs[c4 * 4 + 2][row] = b.z;
            Bs[c4 * 4 + 3][row] = b.w;
        }
        __syncthreads();

        #pragma unroll
        for (int kk = 0; kk < 16; kk++) {
            float ar[8], br[8];
            #pragma unroll
            for (int i = 0; i < 8; i++) ar[i] = As[kk][ty * 8 + i];
            #pragma unroll
            for (int j = 0; j < 8; j++) br[j] = Bs[kk][tx * 8 + j];
            #pragma unroll
            for (int i = 0; i < 8; i++)
                #pragma unroll
                for (int j = 0; j < 8; j++)
                    acc[i][j] += ar[i] * br[j];
        }
        __syncthreads();
    }

    // Epilogue: write logits (guard n < GN)
    #pragma unroll
    for (int i = 0; i < 8; i++) {
        int m = m0 + ty * 8 + i;
        size_t rowoff = (size_t)m * GN;
        #pragma unroll
        for (int j = 0; j < 8; j++) {
            int n = n0 + tx * 8 + j;
            if (n < GN) logits[rowoff + n] = acc[i][j];
        }
    }
}

// ---------------------------------------------------------------------------
// Kernel 2 (fused): per row m:
//   softmax(logits row) -> write similarity out,
//   then concept[m, :] = s[GD]*desc[m, :] + sum_{d: s_d > eps} s_d * vocab[d, :]
// Deterministic ballot-based compaction of the (tiny) surviving weight set.
// Dense fallback keeps correctness if the set overflows SEL_CAP.
// ---------------------------------------------------------------------------
__global__ __launch_bounds__(256) void softmax_blend(
    const float* __restrict__ desc,
    const float* __restrict__ vocab,
    float* __restrict__ sim,           // (GM, GN): logits in, softmax out
    float* __restrict__ outc)          // (GM, GH)
{
    __shared__ float srow[GN + 15];
    __shared__ float red[256];
    __shared__ int wc[8];
    __shared__ unsigned short idxs[SEL_CAP];
    __shared__ int cnt;

    const int m = blockIdx.x;
    const int tid = threadIdx.x;
    float* simrow = sim + (size_t)m * GN;

    // Load logits row into smem
    for (int i = tid; i < GN; i += 256) srow[i] = simrow[i];
    if (tid == 0) cnt = 0;
    __syncthreads();

    // Row max
    float mx = -1e30f;
    for (int i = tid; i < GN; i += 256) mx = fmaxf(mx, srow[i]);
    red[tid] = mx;
    __syncthreads();
    for (int s = 128; s > 0; s >>= 1) {
        if (tid < s) red[tid] = fmaxf(red[tid], red[tid + s]);
        __syncthreads();
    }
    mx = red[0];
    __syncthreads();

    // exp + sum
    float sum = 0.0f;
    for (int i = tid; i < GN; i += 256) {
        float e = expf(srow[i] - mx);
        srow[i] = e;
        sum += e;
    }
    red[tid] = sum;
    __syncthreads();
    for (int s = 128; s > 0; s >>= 1) {
        if (tid < s) red[tid] += red[tid + s];
        __syncthreads();
    }
    float inv = 1.0f / red[0];
    __syncthreads();

    // Normalize in smem + write similarity output
    for (int i = tid; i < GN; i += 256) {
        float v = srow[i] * inv;
        srow[i] = v;
        simrow[i] = v;
    }
    __syncthreads();

    // Deterministic compaction of d < GD with weight > SEL_EPS
    const int warp = tid >> 5;
    const int lane = tid & 31;
    for (int base = 0; base < GD; base += 256) {
        int d = base + tid;
        bool sel = (d < GD) && (srow[d] > SEL_EPS);
        unsigned bal = __ballot_sync(0xffffffffu, sel);
        if (lane == 0) wc[warp] = __popc(bal);
        __syncthreads();
        int off = cnt;
        for (int w = 0; w < warp; w++) off += wc[w];
        int pos = off + __popc(bal & ((1u << lane) - 1u));
        if (sel && pos < SEL_CAP) idxs[pos] = (unsigned short)d;
        __syncthreads();
        if (tid == 0) {
            int t = 0;
            for (int w = 0; w < 8; w++) t += wc[w];
            cnt += t;
        }
        __syncthreads();
    }

    // Blend: each thread owns 4 consecutive h (one float4)
    const float4* d4 = reinterpret_cast<const float4*>(desc + (size_t)m * GH);
    const float4* v4 = reinterpret_cast<const float4*>(vocab);
    float sdef = srow[GD];
    float4 dv = d4[tid];
    float4 acc;
    acc.x = sdef * dv.x;
    acc.y = sdef * dv.y;
    acc.z = sdef * dv.z;
    acc.w = sdef * dv.w;

    int n = cnt;
    if (n <= SEL_CAP) {
        for (int i = 0; i < n; i++) {
            int d = idxs[i];
            float w = srow[d];
            float4 v = v4[(size_t)d * (GH / 4) + tid];
            acc.x += w * v.x;
            acc.y += w * v.y;
            acc.z += w * v.z;
            acc.w += w * v.w;
        }
    } else {
        // Dense fallback (correctness guarantee; effectively never taken)
        for (int d = 0; d < GD; d++) {
            float w = srow[d];
            if (w > SEL_EPS) {
                float4 v = v4[(size_t)d * (GH / 4) + tid];
                acc.x += w * v.x;
                acc.y += w * v.y;
                acc.z += w * v.z;
                acc.w += w * v.w;
            }
        }
    }

    reinterpret_cast<float4*>(outc)[(size_t)m * (GH / 4) + tid] = acc;
}

// ---------------------------------------------------------------------------
extern "C" void kernel_launch(void* const* d_in, const int* in_sizes, int n_in,
                              void* d_out, int out_size)
{
    const float* vocab = (const float*)d_in[0];   // (10000, 1024)
    const float* desc  = (const float*)d_in[1];   // (8, 512, 1024)
    const float* defe  = (const float*)d_in[2];   // (1024,)

    float* outc = (float*)d_out;                       // concept_based (8,512,1024)
    float* sim  = outc + (size_t)GM * GH;              // similarity (8,512,10001)

    dim3 g1((GN + 127) / 128, GM / 128);
    gemm1_logits<<<g1, 256>>>(desc, vocab, defe, sim);
    softmax_blend<<<GM, 256>>>(desc, vocab, sim, outc);
}

// round 4
// speedup vs baseline: 2.2769x; 2.2769x over previous
#include <cuda_runtime.h>
#include <cuda_fp16.h>
#include <stdint.h>

#define GD 10000
#define GN 10001
#define GH 1024
#define GM 4096
#define NPAD 10112          // 79*128 rounded (B tile rows never OOB)

#define MT 128
#define NT 128
#define KT 64
#define NSTAGE 48           // 3 segments x 16 k64-stages (K' = 3072)
#define TPB 256
#define STG_BYTES 32768u    // A(16KB) + B(16KB) per stage
#define SMEM_ALLOC (3u * STG_BYTES)

#define SEL_EPS 1e-10f
#define SEL_CAP 2048

// fp16 split planes (device scratch; .bss, no runtime allocation)
__device__ __half g_Ah[GM * GH];
__device__ __half g_Al[GM * GH];
__device__ __half g_Bh[NPAD * GH];
__device__ __half g_Bl[NPAD * GH];

// ============================ helpers ============================
__device__ __forceinline__ uint32_t smem_u32(const void* p) {
    uint32_t a;
    asm("{ .reg .u64 t; cvta.to.shared.u64 t, %1; cvt.u32.u64 %0, t; }" : "=r"(a) : "l"(p));
    return a;
}
#define CP_ASYNC16(dst, src) \
    asm volatile("cp.async.cg.shared.global [%0], [%1], 16;" :: "r"(dst), "l"(src) : "memory")
#define CP_COMMIT() asm volatile("cp.async.commit_group;" ::: "memory")

#define LDSM4(r, a) \
    asm volatile("ldmatrix.sync.aligned.m8n8.x4.shared.b16 {%0,%1,%2,%3}, [%4];" \
        : "=r"((r)[0]), "=r"((r)[1]), "=r"((r)[2]), "=r"((r)[3]) : "r"(a))

#define MMA16816(c, a, b0, b1) \
    asm volatile("mma.sync.aligned.m16n8k16.row.col.f32.f16.f16.f32 " \
        "{%0,%1,%2,%3}, {%4,%5,%6,%7}, {%8,%9}, {%0,%1,%2,%3};" \
        : "+f"((c)[0]), "+f"((c)[1]), "+f"((c)[2]), "+f"((c)[3]) \
        : "r"((a)[0]), "r"((a)[1]), "r"((a)[2]), "r"((a)[3]), "r"(b0), "r"(b1))

// ============================ split kernels ============================
__global__ __launch_bounds__(256) void split_desc(const float* __restrict__ src) {
    int i = blockIdx.x * 256 + threadIdx.x;          // over GM*GH/2
    if (i >= GM * GH / 2) return;
    float2 v = reinterpret_cast<const float2*>(src)[i];
    __half h0 = __float2half_rn(v.x), h1 = __float2half_rn(v.y);
    __half l0 = __float2half_rn(v.x - __half2float(h0));
    __half l1 = __float2half_rn(v.y - __half2float(h1));
    reinterpret_cast<__half2*>(g_Ah)[i] = __halves2half2(h0, h1);
    reinterpret_cast<__half2*>(g_Al)[i] = __halves2half2(l0, l1);
}

__global__ __launch_bounds__(256) void split_vocab(const float* __restrict__ vocab,
                                                   const float* __restrict__ defemb) {
    int i = blockIdx.x * 256 + threadIdx.x;          // over GN*GH/2
    if (i >= GN * GH / 2) return;
    int row = i / (GH / 2);
    int col = i - row * (GH / 2);
    const float2* s = (row < GD)
        ? reinterpret_cast<const float2*>(vocab) + (size_t)row * (GH / 2) + col
        : reinterpret_cast<const float2*>(defemb) + col;
    float2 v = *s;
    __half h0 = __float2half_rn(v.x), h1 = __float2half_rn(v.y);
    __half l0 = __float2half_rn(v.x - __half2float(h0));
    __half l1 = __float2half_rn(v.y - __half2float(h1));
    size_t o = (size_t)row * (GH / 2) + col;
    reinterpret_cast<__half2*>(g_Bh)[o] = __halves2half2(h0, h1);
    reinterpret_cast<__half2*>(g_Bl)[o] = __halves2half2(l0, l1);
}

// ============================ HMMA GEMM ============================
// logits[m,n] = sum over K'=3072 of split-fp16 products (hh + hl + lh)
__device__ __forceinline__ void load_stage(uint32_t smb, int buf, int s,
                                           int m0, int n0, int tid) {
    const int seg = s >> 4;
    const int kk = (s & 15) * KT;
    const __half* Aseg = (seg < 2) ? g_Ah : g_Al;
    const __half* Bseg = (seg == 1) ? g_Bl : g_Bh;
    const uint32_t ao = smb + (uint32_t)buf * STG_BYTES;
    const uint32_t bo = ao + 16384u;
    const int r0 = tid >> 3, c8 = tid & 7;
    #pragma unroll
    for (int j = 0; j < 4; j++) {
        int row = r0 + j * 32;
        uint32_t x = (uint32_t)(c8 * 16) ^ (uint32_t)((row & 7) << 4);
        CP_ASYNC16(ao + (uint32_t)row * 128u + x,
                   Aseg + (size_t)(m0 + row) * GH + kk + c8 * 8);
        CP_ASYNC16(bo + (uint32_t)row * 128u + x,
                   Bseg + (size_t)(n0 + row) * GH + kk + c8 * 8);
    }
    CP_COMMIT();
}

__global__ __launch_bounds__(TPB) void gemm_hmma(float* __restrict__ logits) {
    extern __shared__ char sm[];
    const uint32_t smb = smem_u32(sm);
    const int tid = threadIdx.x;
    const int wid = tid >> 5, lane = tid & 31;
    const int m0 = blockIdx.y * MT, n0 = blockIdx.x * NT;
    const int wm0 = (wid & 1) * 64, wn0 = (wid >> 1) * 32;

    float acc[4][4][4];
    #pragma unroll
    for (int i = 0; i < 4; i++)
        #pragma unroll
        for (int j = 0; j < 4; j++)
            #pragma unroll
            for (int k = 0; k < 4; k++) acc[i][j][k] = 0.0f;

    // ldmatrix lane->address components
    const int matid = lane >> 3, l7 = lane & 7;
    uint32_t a_base[4], a_xor[4];
    #pragma unroll
    for (int mi = 0; mi < 4; mi++) {
        int row = wm0 + mi * 16 + (matid & 1) * 8 + l7;
        a_base[mi] = (uint32_t)row * 128u;
        a_xor[mi] = (uint32_t)((row & 7) << 4);
    }
    const uint32_t a_colb = (uint32_t)((matid >> 1) * 16);  // byte col offset
    const int brow = wn0 + matid * 8 + l7;
    const uint32_t b_base = 16384u + (uint32_t)brow * 128u;
    const uint32_t b_xor = (uint32_t)((brow & 7) << 4);

    load_stage(smb, 0, 0, m0, n0, tid);
    load_stage(smb, 1, 1, m0, n0, tid);

    for (int s = 0; s < NSTAGE; s++) {
        if (s >= NSTAGE - 2) asm volatile("cp.async.wait_group 0;" ::: "memory");
        else                 asm volatile("cp.async.wait_group 1;" ::: "memory");
        __syncthreads();
        if (s + 2 < NSTAGE) load_stage(smb, (s + 2) % 3, s + 2, m0, n0, tid);

        const uint32_t bufo = smb + (uint32_t)(s % 3) * STG_BYTES;
        #pragma unroll
        for (int k16 = 0; k16 < 4; k16++) {
            const uint32_t kk2 = (uint32_t)(k16 * 32);   // 2*kk bytes
            uint32_t a[4][4], b01[4], b23[4];
            #pragma unroll
            for (int mi = 0; mi < 4; mi++)
                LDSM4(a[mi], bufo + a_base[mi] + ((kk2 + a_colb) ^ a_xor[mi]));
            LDSM4(b01, bufo + b_base + (kk2 ^ b_xor));
            LDSM4(b23, bufo + b_base + ((kk2 + 16u) ^ b_xor));
            #pragma unroll
            for (int mi = 0; mi < 4; mi++)
                #pragma unroll
                for (int ni = 0; ni < 4; ni++)
                    MMA16816(acc[mi][ni], a[mi], b01[ni], b23[ni]);
        }
    }
    // epilogue: guarded scalar stores (GN odd -> no v2 alignment)
    const int gid = lane >> 2, tig = lane & 3;
    #pragma unroll
    for (int mi = 0; mi < 4; mi++) {
        #pragma unroll
        for (int ni = 0; ni < 4; ni++) {
            const int n = n0 + wn0 + ni * 8 + tig * 2;
            const int mrow = m0 + wm0 + mi * 16 + gid;
            float* p0 = logits + (size_t)mrow * GN + n;
            float* p1 = p0 + 8 * (size_t)GN;
            if (n < GN)     { p0[0] = acc[mi][ni][0]; p1[0] = acc[mi][ni][2]; }
            if (n + 1 < GN) { p0[1] = acc[mi][ni][1]; p1[1] = acc[mi][ni][3]; }
        }
    }
}

// ============================ softmax + sparse blend ============================
__global__ __launch_bounds__(256) void softmax_blend(
    const float* __restrict__ desc,
    const float* __restrict__ vocab,
    float* __restrict__ sim,
    float* __restrict__ outc)
{
    __shared__ float srow[GN + 15];
    __shared__ float red[256];
    __shared__ int wc[8];
    __shared__ unsigned short idxs[SEL_CAP];
    __shared__ int cnt;

    const int m = blockIdx.x;
    const int tid = threadIdx.x;
    float* simrow = sim + (size_t)m * GN;

    for (int i = tid; i < GN; i += 256) srow[i] = simrow[i];
    if (tid == 0) cnt = 0;
    __syncthreads();

    float mx = -1e30f;
    for (int i = tid; i < GN; i += 256) mx = fmaxf(mx, srow[i]);
    red[tid] = mx;
    __syncthreads();
    for (int s = 128; s > 0; s >>= 1) {
        if (tid < s) red[tid] = fmaxf(red[tid], red[tid + s]);
        __syncthreads();
    }
    mx = red[0];
    __syncthreads();

    float sum = 0.0f;
    for (int i = tid; i < GN; i += 256) {
        float e = expf(srow[i] - mx);
        srow[i] = e;
        sum += e;
    }
    red[tid] = sum;
    __syncthreads();
    for (int s = 128; s > 0; s >>= 1) {
        if (tid < s) red[tid] += red[tid + s];
        __syncthreads();
    }
    float inv = 1.0f / red[0];
    __syncthreads();

    for (int i = tid; i < GN; i += 256) {
        float v = srow[i] * inv;
        srow[i] = v;
        simrow[i] = v;
    }
    __syncthreads();

    const int warp = tid >> 5;
    const int lane = tid & 31;
    for (int base = 0; base < GD; base += 256) {
        int d = base + tid;
        bool sel = (d < GD) && (srow[d] > SEL_EPS);
        unsigned bal = __ballot_sync(0xffffffffu, sel);
        if (lane == 0) wc[warp] = __popc(bal);
        __syncthreads();
        int off = cnt;
        for (int w = 0; w < warp; w++) off += wc[w];
        int pos = off + __popc(bal & ((1u << lane) - 1u));
        if (sel && pos < SEL_CAP) idxs[pos] = (unsigned short)d;
        __syncthreads();
        if (tid == 0) {
            int t = 0;
            for (int w = 0; w < 8; w++) t += wc[w];
            cnt += t;
        }
        __syncthreads();
    }

    const float4* d4 = reinterpret_cast<const float4*>(desc + (size_t)m * GH);
    const float4* v4 = reinterpret_cast<const float4*>(vocab);
    float sdef = srow[GD];
    float4 dv = d4[tid];
    float4 acc;
    acc.x = sdef * dv.x; acc.y = sdef * dv.y; acc.z = sdef * dv.z; acc.w = sdef * dv.w;

    int n = cnt;
    if (n <= SEL_CAP) {
        for (int i = 0; i < n; i++) {
            int d = idxs[i];
            float w = srow[d];
            float4 v = v4[(size_t)d * (GH / 4) + tid];
            acc.x += w * v.x; acc.y += w * v.y; acc.z += w * v.z; acc.w += w * v.w;
        }
    } else {
        for (int d = 0; d < GD; d++) {
            float w = srow[d];
            if (w > SEL_EPS) {
                float4 v = v4[(size_t)d * (GH / 4) + tid];
                acc.x += w * v.x; acc.y += w * v.y; acc.z += w * v.z; acc.w += w * v.w;
            }
        }
    }
    reinterpret_cast<float4*>(outc)[(size_t)m * (GH / 4) + tid] = acc;
}

// ============================ launcher ============================
extern "C" void kernel_launch(void* const* d_in, const int* in_sizes, int n_in,
                              void* d_out, int out_size)
{
    const float* vocab = (const float*)d_in[0];   // (10000, 1024)
    const float* desc  = (const float*)d_in[1];   // (8, 512, 1024)
    const float* defe  = (const float*)d_in[2];   // (1024,)

    float* outc = (float*)d_out;
    float* sim  = outc + (size_t)GM * GH;

    cudaFuncSetAttribute(gemm_hmma, cudaFuncAttributeMaxDynamicSharedMemorySize, SMEM_ALLOC);

    split_desc<<<(GM * GH / 2 + 255) / 256, 256>>>(desc);
    split_vocab<<<(GN * GH / 2 + 255) / 256, 256>>>(vocab, defe);

    dim3 g1((GN + NT - 1) / NT, GM / MT);   // (79, 32)
    gemm_hmma<<<g1, TPB, SMEM_ALLOC>>>(sim);
    softmax_blend<<<GM, 256>>>(desc, vocab, sim, outc);
}

// round 5
// speedup vs baseline: 2.2777x; 1.0004x over previous
#include <cuda_runtime.h>
#include <cuda_fp16.h>
#include <stdint.h>

#define GD 10000
#define GN 10001
#define GH 1024
#define GM 4096
#define NPAD 10112          // 79*128 rounded (B tile rows never OOB)

#define MT 128
#define NT 128
#define KT 64
#define NSTAGE 48           // 3 segments x 16 k64-stages (K' = 3072)
#define TPB 256
#define STG_BYTES 32768u    // A(16KB) + B(16KB) per stage
#define SMEM_ALLOC (3u * STG_BYTES)

#define SEL_EPS 1e-10f
#define SEL_CAP 2048

// fp16 split planes (device scratch; .bss, no runtime allocation)
__device__ __half g_Ah[GM * GH];
__device__ __half g_Al[GM * GH];
__device__ __half g_Bh[NPAD * GH];
__device__ __half g_Bl[NPAD * GH];

// ============================ helpers ============================
__device__ __forceinline__ uint32_t smem_u32(const void* p) {
    uint32_t a;
    asm("{ .reg .u64 t; cvta.to.shared.u64 t, %1; cvt.u32.u64 %0, t; }" : "=r"(a) : "l"(p));
    return a;
}
#define CP_ASYNC16(dst, src) \
    asm volatile("cp.async.cg.shared.global [%0], [%1], 16;" :: "r"(dst), "l"(src) : "memory")
#define CP_COMMIT() asm volatile("cp.async.commit_group;" ::: "memory")

#define LDSM4(r, a) \
    asm volatile("ldmatrix.sync.aligned.m8n8.x4.shared.b16 {%0,%1,%2,%3}, [%4];" \
        : "=r"((r)[0]), "=r"((r)[1]), "=r"((r)[2]), "=r"((r)[3]) : "r"(a))

#define MMA16816(c, a, b0, b1) \
    asm volatile("mma.sync.aligned.m16n8k16.row.col.f32.f16.f16.f32 " \
        "{%0,%1,%2,%3}, {%4,%5,%6,%7}, {%8,%9}, {%0,%1,%2,%3};" \
        : "+f"((c)[0]), "+f"((c)[1]), "+f"((c)[2]), "+f"((c)[3]) \
        : "r"((a)[0]), "r"((a)[1]), "r"((a)[2]), "r"((a)[3]), "r"(b0), "r"(b1))

// ============================ split kernels ============================
__global__ __launch_bounds__(256) void split_desc(const float* __restrict__ src) {
    int i = blockIdx.x * 256 + threadIdx.x;          // over GM*GH/2
    if (i >= GM * GH / 2) return;
    float2 v = reinterpret_cast<const float2*>(src)[i];
    __half h0 = __float2half_rn(v.x), h1 = __float2half_rn(v.y);
    __half l0 = __float2half_rn(v.x - __half2float(h0));
    __half l1 = __float2half_rn(v.y - __half2float(h1));
    reinterpret_cast<__half2*>(g_Ah)[i] = __halves2half2(h0, h1);
    reinterpret_cast<__half2*>(g_Al)[i] = __halves2half2(l0, l1);
}

__global__ __launch_bounds__(256) void split_vocab(const float* __restrict__ vocab,
                                                   const float* __restrict__ defemb) {
    int i = blockIdx.x * 256 + threadIdx.x;          // over GN*GH/2
    if (i >= GN * GH / 2) return;
    int row = i / (GH / 2);
    int col = i - row * (GH / 2);
    const float2* s = (row < GD)
        ? reinterpret_cast<const float2*>(vocab) + (size_t)row * (GH / 2) + col
        : reinterpret_cast<const float2*>(defemb) + col;
    float2 v = *s;
    __half h0 = __float2half_rn(v.x), h1 = __float2half_rn(v.y);
    __half l0 = __float2half_rn(v.x - __half2float(h0));
    __half l1 = __float2half_rn(v.y - __half2float(h1));
    size_t o = (size_t)row * (GH / 2) + col;
    reinterpret_cast<__half2*>(g_Bh)[o] = __halves2half2(h0, h1);
    reinterpret_cast<__half2*>(g_Bl)[o] = __halves2half2(l0, l1);
}

// ============================ HMMA GEMM ============================
// logits[m,n] = sum over K'=3072 of split-fp16 products (hh + hl + lh)
__device__ __forceinline__ void load_stage(uint32_t smb, int buf, int s,
                                           int m0, int n0, int tid) {
    const int seg = s >> 4;
    const int kk = (s & 15) * KT;
    const __half* Aseg = (seg < 2) ? g_Ah : g_Al;
    const __half* Bseg = (seg == 1) ? g_Bl : g_Bh;
    const uint32_t ao = smb + (uint32_t)buf * STG_BYTES;
    const uint32_t bo = ao + 16384u;
    const int r0 = tid >> 3, c8 = tid & 7;
    #pragma unroll
    for (int j = 0; j < 4; j++) {
        int row = r0 + j * 32;
        uint32_t x = (uint32_t)(c8 * 16) ^ (uint32_t)((row & 7) << 4);
        CP_ASYNC16(ao + (uint32_t)row * 128u + x,
                   Aseg + (size_t)(m0 + row) * GH + kk + c8 * 8);
        CP_ASYNC16(bo + (uint32_t)row * 128u + x,
                   Bseg + (size_t)(n0 + row) * GH + kk + c8 * 8);
    }
    CP_COMMIT();
}

__global__ __launch_bounds__(TPB) void gemm_hmma(float* __restrict__ logits) {
    extern __shared__ char sm[];
    const uint32_t smb = smem_u32(sm);
    const int tid = threadIdx.x;
    const int wid = tid >> 5, lane = tid & 31;
    const int m0 = blockIdx.y * MT, n0 = blockIdx.x * NT;
    const int wm0 = (wid & 1) * 64, wn0 = (wid >> 1) * 32;

    float acc[4][4][4];
    #pragma unroll
    for (int i = 0; i < 4; i++)
        #pragma unroll
        for (int j = 0; j < 4; j++)
            #pragma unroll
            for (int k = 0; k < 4; k++) acc[i][j][k] = 0.0f;

    // ldmatrix lane->address components
    const int matid = lane >> 3, l7 = lane & 7;
    uint32_t a_base[4], a_xor[4];
    #pragma unroll
    for (int mi = 0; mi < 4; mi++) {
        int row = wm0 + mi * 16 + (matid & 1) * 8 + l7;
        a_base[mi] = (uint32_t)row * 128u;
        a_xor[mi] = (uint32_t)((row & 7) << 4);
    }
    const uint32_t a_colb = (uint32_t)((matid >> 1) * 16);  // byte col offset
    const int brow = wn0 + matid * 8 + l7;
    const uint32_t b_base = 16384u + (uint32_t)brow * 128u;
    const uint32_t b_xor = (uint32_t)((brow & 7) << 4);

    load_stage(smb, 0, 0, m0, n0, tid);
    load_stage(smb, 1, 1, m0, n0, tid);

    for (int s = 0; s < NSTAGE; s++) {
        if (s >= NSTAGE - 2) asm volatile("cp.async.wait_group 0;" ::: "memory");
        else                 asm volatile("cp.async.wait_group 1;" ::: "memory");
        __syncthreads();
        if (s + 2 < NSTAGE) load_stage(smb, (s + 2) % 3, s + 2, m0, n0, tid);

        const uint32_t bufo = smb + (uint32_t)(s % 3) * STG_BYTES;
        #pragma unroll
        for (int k16 = 0; k16 < 4; k16++) {
            const uint32_t kk2 = (uint32_t)(k16 * 32);   // 2*kk bytes
            uint32_t a[4][4], b01[4], b23[4];
            #pragma unroll
            for (int mi = 0; mi < 4; mi++)
                LDSM4(a[mi], bufo + a_base[mi] + ((kk2 + a_colb) ^ a_xor[mi]));
            LDSM4(b01, bufo + b_base + (kk2 ^ b_xor));
            LDSM4(b23, bufo + b_base + ((kk2 + 16u) ^ b_xor));
            #pragma unroll
            for (int mi = 0; mi < 4; mi++)
                #pragma unroll
                for (int ni = 0; ni < 4; ni++)
                    MMA16816(acc[mi][ni], a[mi], b01[ni], b23[ni]);
        }
    }
    // epilogue: guarded scalar stores (GN odd -> no v2 alignment)
    const int gid = lane >> 2, tig = lane & 3;
    #pragma unroll
    for (int mi = 0; mi < 4; mi++) {
        #pragma unroll
        for (int ni = 0; ni < 4; ni++) {
            const int n = n0 + wn0 + ni * 8 + tig * 2;
            const int mrow = m0 + wm0 + mi * 16 + gid;
            float* p0 = logits + (size_t)mrow * GN + n;
            float* p1 = p0 + 8 * (size_t)GN;
            if (n < GN)     { p0[0] = acc[mi][ni][0]; p1[0] = acc[mi][ni][2]; }
            if (n + 1 < GN) { p0[1] = acc[mi][ni][1]; p1[1] = acc[mi][ni][3]; }
        }
    }
}

// ============================ softmax + sparse blend ============================
__global__ __launch_bounds__(256) void softmax_blend(
    const float* __restrict__ desc,
    const float* __restrict__ vocab,
    float* __restrict__ sim,
    float* __restrict__ outc)
{
    __shared__ float srow[GN + 15];
    __shared__ float red[256];
    __shared__ int wc[8];
    __shared__ unsigned short idxs[SEL_CAP];
    __shared__ int cnt;

    const int m = blockIdx.x;
    const int tid = threadIdx.x;
    float* simrow = sim + (size_t)m * GN;

    for (int i = tid; i < GN; i += 256) srow[i] = simrow[i];
    if (tid == 0) cnt = 0;
    __syncthreads();

    float mx = -1e30f;
    for (int i = tid; i < GN; i += 256) mx = fmaxf(mx, srow[i]);
    red[tid] = mx;
    __syncthreads();
    for (int s = 128; s > 0; s >>= 1) {
        if (tid < s) red[tid] = fmaxf(red[tid], red[tid + s]);
        __syncthreads();
    }
    mx = red[0];
    __syncthreads();

    float sum = 0.0f;
    for (int i = tid; i < GN; i += 256) {
        float e = expf(srow[i] - mx);
        srow[i] = e;
        sum += e;
    }
    red[tid] = sum;
    __syncthreads();
    for (int s = 128; s > 0; s >>= 1) {
        if (tid < s) red[tid] += red[tid + s];
        __syncthreads();
    }
    float inv = 1.0f / red[0];
    __syncthreads();

    for (int i = tid; i < GN; i += 256) {
        float v = srow[i] * inv;
        srow[i] = v;
        simrow[i] = v;
    }
    __syncthreads();

    const int warp = tid >> 5;
    const int lane = tid & 31;
    for (int base = 0; base < GD; base += 256) {
        int d = base + tid;
        bool sel = (d < GD) && (srow[d] > SEL_EPS);
        unsigned bal = __ballot_sync(0xffffffffu, sel);
        if (lane == 0) wc[warp] = __popc(bal);
        __syncthreads();
        int off = cnt;
        for (int w = 0; w < warp; w++) off += wc[w];
        int pos = off + __popc(bal & ((1u << lane) - 1u));
        if (sel && pos < SEL_CAP) idxs[pos] = (unsigned short)d;
        __syncthreads();
        if (tid == 0) {
            int t = 0;
            for (int w = 0; w < 8; w++) t += wc[w];
            cnt += t;
        }
        __syncthreads();
    }

    const float4* d4 = reinterpret_cast<const float4*>(desc + (size_t)m * GH);
    const float4* v4 = reinterpret_cast<const float4*>(vocab);
    float sdef = srow[GD];
    float4 dv = d4[tid];
    float4 acc;
    acc.x = sdef * dv.x; acc.y = sdef * dv.y; acc.z = sdef * dv.z; acc.w = sdef * dv.w;

    int n = cnt;
    if (n <= SEL_CAP) {
        for (int i = 0; i < n; i++) {
            int d = idxs[i];
            float w = srow[d];
            float4 v = v4[(size_t)d * (GH / 4) + tid];
            acc.x += w * v.x; acc.y += w * v.y; acc.z += w * v.z; acc.w += w * v.w;
        }
    } else {
        for (int d = 0; d < GD; d++) {
            float w = srow[d];
            if (w > SEL_EPS) {
                float4 v = v4[(size_t)d * (GH / 4) + tid];
                acc.x += w * v.x; acc.y += w * v.y; acc.z += w * v.z; acc.w += w * v.w;
            }
        }
    }
    reinterpret_cast<float4*>(outc)[(size_t)m * (GH / 4) + tid] = acc;
}

// ============================ launcher ============================
extern "C" void kernel_launch(void* const* d_in, const int* in_sizes, int n_in,
                              void* d_out, int out_size)
{
    const float* vocab = (const float*)d_in[0];   // (10000, 1024)
    const float* desc  = (const float*)d_in[1];   // (8, 512, 1024)
    const float* defe  = (const float*)d_in[2];   // (1024,)

    float* outc = (float*)d_out;
    float* sim  = outc + (size_t)GM * GH;

    cudaFuncSetAttribute(gemm_hmma, cudaFuncAttributeMaxDynamicSharedMemorySize, SMEM_ALLOC);

    split_desc<<<(GM * GH / 2 + 255) / 256, 256>>>(desc);
    split_vocab<<<(GN * GH / 2 + 255) / 256, 256>>>(vocab, defe);

    dim3 g1((GN + NT - 1) / NT, GM / MT);   // (79, 32)
    gemm_hmma<<<g1, TPB, SMEM_ALLOC>>>(sim);
    softmax_blend<<<GM, 256>>>(desc, vocab, sim, outc);
}

// round 6
// speedup vs baseline: 3.8437x; 1.6875x over previous
#include <cuda_runtime.h>
#include <cuda_fp16.h>
#include <stdint.h>

#define GD 10000
#define GN 10001
#define GH 1024
#define GM 4096
#define NPAD 10112

#define MT 128
#define NT 128
#define KT 64
#define NSTAGE 16           // K = 1024, fp16-hi term only
#define TPB 256
#define STG_BYTES 32768u
#define SMEM_ALLOC (3u * STG_BYTES)

#define SEL_EPS 1e-10f
#define CAND_SLACK 45.0f
#define WCAP 64             // per-warp candidate capacity

// fp16 hi planes (device scratch, .bss)
__device__ __half g_Ah[GM * GH];
__device__ __half g_Bh[NPAD * GH];

// ============================ helpers ============================
__device__ __forceinline__ uint32_t smem_u32(const void* p) {
    uint32_t a;
    asm("{ .reg .u64 t; cvta.to.shared.u64 t, %1; cvt.u32.u64 %0, t; }" : "=r"(a) : "l"(p));
    return a;
}
#define CP_ASYNC16(dst, src) \
    asm volatile("cp.async.cg.shared.global [%0], [%1], 16;" :: "r"(dst), "l"(src) : "memory")
#define CP_COMMIT() asm volatile("cp.async.commit_group;" ::: "memory")

#define LDSM4(r, a) \
    asm volatile("ldmatrix.sync.aligned.m8n8.x4.shared.b16 {%0,%1,%2,%3}, [%4];" \
        : "=r"((r)[0]), "=r"((r)[1]), "=r"((r)[2]), "=r"((r)[3]) : "r"(a))

#define MMA16816(c, a, b0, b1) \
    asm volatile("mma.sync.aligned.m16n8k16.row.col.f32.f16.f16.f32 " \
        "{%0,%1,%2,%3}, {%4,%5,%6,%7}, {%8,%9}, {%0,%1,%2,%3};" \
        : "+f"((c)[0]), "+f"((c)[1]), "+f"((c)[2]), "+f"((c)[3]) \
        : "r"((a)[0]), "r"((a)[1]), "r"((a)[2]), "r"((a)[3]), "r"(b0), "r"(b1))

// ============================ cast kernels (fp32 -> fp16 hi) ============================
__global__ __launch_bounds__(256) void cast_desc(const float* __restrict__ src) {
    int i = blockIdx.x * 256 + threadIdx.x;           // float4 index
    if (i >= GM * GH / 4) return;
    float4 v = reinterpret_cast<const float4*>(src)[i];
    __half2* dst = reinterpret_cast<__half2*>(g_Ah);
    dst[2 * i]     = __floats2half2_rn(v.x, v.y);
    dst[2 * i + 1] = __floats2half2_rn(v.z, v.w);
}

__global__ __launch_bounds__(256) void cast_vocab(const float* __restrict__ vocab,
                                                  const float* __restrict__ defemb) {
    int i = blockIdx.x * 256 + threadIdx.x;           // float4 index over GN*GH/4
    if (i >= GN * GH / 4) return;
    int row = i >> 8;                                 // 256 float4 per row
    int col = i & 255;
    float4 v = (row < GD)
        ? reinterpret_cast<const float4*>(vocab)[(size_t)row * 256 + col]
        : reinterpret_cast<const float4*>(defemb)[col];
    __half2* dst = reinterpret_cast<__half2*>(g_Bh);
    dst[2 * i]     = __floats2half2_rn(v.x, v.y);
    dst[2 * i + 1] = __floats2half2_rn(v.z, v.w);
}

// ============================ HMMA GEMM (hh term, K=1024) ============================
__device__ __forceinline__ void load_stage(uint32_t smb, int buf, int s,
                                           int m0, int n0, int tid) {
    const int kk = s * KT;
    const uint32_t ao = smb + (uint32_t)buf * STG_BYTES;
    const uint32_t bo = ao + 16384u;
    const int r0 = tid >> 3, c8 = tid & 7;
    #pragma unroll
    for (int j = 0; j < 4; j++) {
        int row = r0 + j * 32;
        uint32_t x = (uint32_t)(c8 * 16) ^ (uint32_t)((row & 7) << 4);
        CP_ASYNC16(ao + (uint32_t)row * 128u + x,
                   g_Ah + (size_t)(m0 + row) * GH + kk + c8 * 8);
        CP_ASYNC16(bo + (uint32_t)row * 128u + x,
                   g_Bh + (size_t)(n0 + row) * GH + kk + c8 * 8);
    }
    CP_COMMIT();
}

__global__ __launch_bounds__(TPB, 2) void gemm_hmma(float* __restrict__ logits) {
    extern __shared__ char sm[];
    const uint32_t smb = smem_u32(sm);
    const int tid = threadIdx.x;
    const int wid = tid >> 5, lane = tid & 31;
    const int m0 = blockIdx.y * MT, n0 = blockIdx.x * NT;
    const int wm0 = (wid & 1) * 64, wn0 = (wid >> 1) * 32;

    float acc[4][4][4];
    #pragma unroll
    for (int i = 0; i < 4; i++)
        #pragma unroll
        for (int j = 0; j < 4; j++)
            #pragma unroll
            for (int k = 0; k < 4; k++) acc[i][j][k] = 0.0f;

    const int matid = lane >> 3, l7 = lane & 7;
    uint32_t a_base[4], a_xor[4];
    #pragma unroll
    for (int mi = 0; mi < 4; mi++) {
        int row = wm0 + mi * 16 + (matid & 1) * 8 + l7;
        a_base[mi] = (uint32_t)row * 128u;
        a_xor[mi] = (uint32_t)((row & 7) << 4);
    }
    const uint32_t a_colb = (uint32_t)((matid >> 1) * 16);
    const int brow = wn0 + matid * 8 + l7;
    const uint32_t b_base = 16384u + (uint32_t)brow * 128u;
    const uint32_t b_xor = (uint32_t)((brow & 7) << 4);

    load_stage(smb, 0, 0, m0, n0, tid);
    load_stage(smb, 1, 1, m0, n0, tid);

    for (int s = 0; s < NSTAGE; s++) {
        if (s >= NSTAGE - 2) asm volatile("cp.async.wait_group 0;" ::: "memory");
        else                 asm volatile("cp.async.wait_group 1;" ::: "memory");
        __syncthreads();
        if (s + 2 < NSTAGE) load_stage(smb, (s + 2) % 3, s + 2, m0, n0, tid);

        const uint32_t bufo = smb + (uint32_t)(s % 3) * STG_BYTES;
        #pragma unroll
        for (int k16 = 0; k16 < 4; k16++) {
            const uint32_t kk2 = (uint32_t)(k16 * 32);
            uint32_t a[4][4], b01[4], b23[4];
            #pragma unroll
            for (int mi = 0; mi < 4; mi++)
                LDSM4(a[mi], bufo + a_base[mi] + ((kk2 + a_colb) ^ a_xor[mi]));
            LDSM4(b01, bufo + b_base + (kk2 ^ b_xor));
            LDSM4(b23, bufo + b_base + ((kk2 + 16u) ^ b_xor));
            #pragma unroll
            for (int mi = 0; mi < 4; mi++)
                #pragma unroll
                for (int ni = 0; ni < 4; ni++)
                    MMA16816(acc[mi][ni], a[mi], b01[ni], b23[ni]);
        }
    }
    const int gid = lane >> 2, tig = lane & 3;
    #pragma unroll
    for (int mi = 0; mi < 4; mi++) {
        #pragma unroll
        for (int ni = 0; ni < 4; ni++) {
            const int n = n0 + wn0 + ni * 8 + tig * 2;
            const int mrow = m0 + wm0 + mi * 16 + gid;
            float* p0 = logits + (size_t)mrow * GN + n;
            float* p1 = p0 + 8 * (size_t)GN;
            if (n < GN)     { p0[0] = acc[mi][ni][0]; p1[0] = acc[mi][ni][2]; }
            if (n + 1 < GN) { p0[1] = acc[mi][ni][1]; p1[1] = acc[mi][ni][3]; }
        }
    }
}

// ============================ fused refine + softmax + blend ============================
// Per row: hh logits in sim. Find hh max, select candidates (> max-45),
// recompute their logits exactly in fp32, softmax whole row, sparse blend.
__global__ __launch_bounds__(256) void softmax_blend(
    const float* __restrict__ desc,
    const float* __restrict__ vocab,
    const float* __restrict__ defemb,
    float* __restrict__ sim,
    float* __restrict__ outc)
{
    __shared__ float srow[GN + 3];
    __shared__ float drow[GH];
    __shared__ float red[256];
    __shared__ unsigned short bidx[8 * WCAP];
    __shared__ unsigned short cidx[8 * WCAP];
    __shared__ int wcnt[8];

    const int m = blockIdx.x;
    const int tid = threadIdx.x;
    const int wid = tid >> 5, lane = tid & 31;
    float* simrow = sim + (size_t)m * GN;

    // desc row -> smem (float4)
    {
        const float4* s4 = reinterpret_cast<const float4*>(desc + (size_t)m * GH);
        reinterpret_cast<float4*>(drow)[tid] = s4[tid];
    }
    // load hh logits + row max
    float mx = -1e30f;
    for (int i = tid; i < GN; i += 256) {
        float v = simrow[i];
        srow[i] = v;
        mx = fmaxf(mx, v);
    }
    red[tid] = mx;
    __syncthreads();
    for (int s = 128; s > 0; s >>= 1) {
        if (tid < s) red[tid] = fmaxf(red[tid], red[tid + s]);
        __syncthreads();
    }
    const float mx0 = red[0];
    __syncthreads();

    // per-warp candidate scan (no block syncs inside)
    {
        const float thr = mx0 - CAND_SLACK;
        const int start = wid * 1251;
        const int end = min(start + 1251, GN);
        int c = 0;
        for (int base = start; base < end; base += 32) {
            int d = base + lane;
            bool sel = (d < end) && (srow[d] > thr);
            unsigned bal = __ballot_sync(0xffffffffu, sel);
            int pos = c + __popc(bal & ((1u << lane) - 1u));
            if (sel && pos < WCAP) bidx[wid * WCAP + pos] = (unsigned short)d;
            c += __popc(bal);
        }
        if (lane == 0) wcnt[wid] = min(c, WCAP);
    }
    __syncthreads();

    // flatten buckets -> cidx (deterministic order)
    int cnt = 0;
    {
        int offs[8];
        #pragma unroll
        for (int w = 0; w < 8; w++) { offs[w] = cnt; cnt += wcnt[w]; }
        for (int i = lane; i < wcnt[wid]; i += 32)
            cidx[offs[wid] + i] = bidx[wid * WCAP + i];
    }
    __syncthreads();

    // exact fp32 refinement: candidate g handled by warp (g % 8)
    for (int g = wid; g < cnt; g += 8) {
        const int d = cidx[g];
        const float4* v4 = (d < GD)
            ? reinterpret_cast<const float4*>(vocab + (size_t)d * GH)
            : reinterpret_cast<const float4*>(defemb);
        const float4* d4 = reinterpret_cast<const float4*>(drow);
        float s = 0.0f;
        #pragma unroll
        for (int e = 0; e < 8; e++) {
            float4 a = d4[lane + e * 32];
            float4 b = v4[lane + e * 32];
            s = fmaf(a.x, b.x, s); s = fmaf(a.y, b.y, s);
            s = fmaf(a.z, b.z, s); s = fmaf(a.w, b.w, s);
        }
        #pragma unroll
        for (int o = 16; o > 0; o >>= 1) s += __shfl_xor_sync(0xffffffffu, s, o);
        if (lane == 0) srow[d] = s;
    }
    __syncthreads();

    // refined max (true max is always a candidate)
    mx = -1e30f;
    for (int g = tid; g < cnt; g += 256) mx = fmaxf(mx, srow[cidx[g]]);
    red[tid] = mx;
    __syncthreads();
    for (int s = 128; s > 0; s >>= 1) {
        if (tid < s) red[tid] = fmaxf(red[tid], red[tid + s]);
        __syncthreads();
    }
    mx = red[0];
    __syncthreads();

    // exp + sum
    float sum = 0.0f;
    for (int i = tid; i < GN; i += 256) {
        float e = __expf(srow[i] - mx);
        srow[i] = e;
        sum += e;
    }
    red[tid] = sum;
    __syncthreads();
    for (int s = 128; s > 0; s >>= 1) {
        if (tid < s) red[tid] += red[tid + s];
        __syncthreads();
    }
    const float inv = 1.0f / red[0];
    __syncthreads();

    // normalize + write similarity
    for (int i = tid; i < GN; i += 256) {
        float v = srow[i] * inv;
        srow[i] = v;
        simrow[i] = v;
    }
    __syncthreads();

    // sparse blend over the candidate set
    float4 dv = reinterpret_cast<const float4*>(drow)[tid];
    const float sdef = srow[GD];
    float4 acc;
    acc.x = sdef * dv.x; acc.y = sdef * dv.y; acc.z = sdef * dv.z; acc.w = sdef * dv.w;

    const float4* v4 = reinterpret_cast<const float4*>(vocab);
    for (int g = 0; g < cnt; g++) {
        const int d = cidx[g];
        if (d < GD) {
            const float w = srow[d];
            if (w > SEL_EPS) {
                float4 v = v4[(size_t)d * (GH / 4) + tid];
                acc.x = fmaf(w, v.x, acc.x); acc.y = fmaf(w, v.y, acc.y);
                acc.z = fmaf(w, v.z, acc.z); acc.w = fmaf(w, v.w, acc.w);
            }
        }
    }
    reinterpret_cast<float4*>(outc)[(size_t)m * (GH / 4) + tid] = acc;
}

// ============================ launcher ============================
extern "C" void kernel_launch(void* const* d_in, const int* in_sizes, int n_in,
                              void* d_out, int out_size)
{
    const float* vocab = (const float*)d_in[0];   // (10000, 1024)
    const float* desc  = (const float*)d_in[1];   // (8, 512, 1024)
    const float* defe  = (const float*)d_in[2];   // (1024,)

    float* outc = (float*)d_out;
    float* sim  = outc + (size_t)GM * GH;

    cudaFuncSetAttribute(gemm_hmma, cudaFuncAttributeMaxDynamicSharedMemorySize, SMEM_ALLOC);

    cast_desc<<<GM * GH / 4 / 256, 256>>>(desc);
    cast_vocab<<<(GN * GH / 4 + 255) / 256, 256>>>(vocab, defe);

    dim3 g1((GN + NT - 1) / NT, GM / MT);   // (79, 32)
    gemm_hmma<<<g1, TPB, SMEM_ALLOC>>>(sim);
    softmax_blend<<<GM, 256>>>(desc, vocab, defe, sim, outc);
}